// round 16
// baseline (speedup 1.0000x reference)
#include <cuda_runtime.h>

#define BB 16
#define NN 512   // seq1 rows (columns of transposed cost)
#define MM 448   // seq2 rows (rows of transposed cost)
#define DD 1536
#define FULL 0xffffffffu

// cost_t[b][m][n] = ||seq1[b][n] - seq2[b][m]||  (transposed layout for JV)
__device__ float g_cost[BB * MM * NN];
__device__ float g_n1[BB * NN];
__device__ float g_n2[BB * MM];
__device__ int   g_perm[BB * NN];

// ---------------------------------------------------------------------------
// Row norms: one warp per row.
// ---------------------------------------------------------------------------
__global__ void norms_kernel(const float* __restrict__ seq1,
                             const float* __restrict__ seq2) {
    int warp = (blockIdx.x * blockDim.x + threadIdx.x) >> 5;
    int lane = threadIdx.x & 31;
    int total = BB * (NN + MM);
    if (warp >= total) return;
    const float* ptr;
    float* out;
    if (warp < BB * NN) {
        ptr = seq1 + (size_t)warp * DD;
        out = g_n1 + warp;
    } else {
        int w = warp - BB * NN;
        ptr = seq2 + (size_t)w * DD;
        out = g_n2 + w;
    }
    float s = 0.f;
    for (int k = lane * 4; k < DD; k += 32 * 4) {
        float4 v = *(const float4*)(ptr + k);
        s += v.x * v.x + v.y * v.y + v.z * v.z + v.w * v.w;
    }
#pragma unroll
    for (int o = 16; o > 0; o >>= 1) s += __shfl_down_sync(FULL, s, o);
    if (lane == 0) *out = s;
}

// ---------------------------------------------------------------------------
// Cost matrix: tiled fp32 GEMM, 64(m) x 128(n) tile, 8x4 per thread.
// ---------------------------------------------------------------------------
#define TBM 64
#define TBN 128
#define TBK 16

__global__ void __launch_bounds__(256) cost_kernel(const float* __restrict__ seq1,
                                                   const float* __restrict__ seq2) {
    __shared__ float As[TBK][TBM + 4];
    __shared__ float Bs[TBK][TBN + 4];

    int b  = blockIdx.z;
    int m0 = blockIdx.y * TBM;
    int n0 = blockIdx.x * TBN;
    const float* A  = seq2 + ((size_t)b * MM + m0) * DD;
    const float* Bp = seq1 + ((size_t)b * NN + n0) * DD;

    int tid = threadIdx.x;
    int lr  = tid >> 2;          // 0..63
    int lc  = (tid & 3) * 4;     // 0,4,8,12
    int ty  = tid >> 5;          // 0..7
    int tx  = tid & 31;          // 0..31

    float acc[8][4] = {};

    for (int k0 = 0; k0 < DD; k0 += TBK) {
        float4 av  = *(const float4*)(A  + (size_t)lr * DD + k0 + lc);
        float4 bv0 = *(const float4*)(Bp + (size_t)lr * DD + k0 + lc);
        float4 bv1 = *(const float4*)(Bp + (size_t)(lr + 64) * DD + k0 + lc);
        __syncthreads();
        As[lc + 0][lr] = av.x;  As[lc + 1][lr] = av.y;
        As[lc + 2][lr] = av.z;  As[lc + 3][lr] = av.w;
        Bs[lc + 0][lr] = bv0.x; Bs[lc + 1][lr] = bv0.y;
        Bs[lc + 2][lr] = bv0.z; Bs[lc + 3][lr] = bv0.w;
        Bs[lc + 0][lr + 64] = bv1.x; Bs[lc + 1][lr + 64] = bv1.y;
        Bs[lc + 2][lr + 64] = bv1.z; Bs[lc + 3][lr + 64] = bv1.w;
        __syncthreads();
#pragma unroll
        for (int k = 0; k < TBK; k++) {
            float4 a0 = *(const float4*)&As[k][ty * 8];
            float4 a1 = *(const float4*)&As[k][ty * 8 + 4];
            float4 bb = *(const float4*)&Bs[k][tx * 4];
            float ar[8] = {a0.x, a0.y, a0.z, a0.w, a1.x, a1.y, a1.z, a1.w};
            float br[4] = {bb.x, bb.y, bb.z, bb.w};
#pragma unroll
            for (int im = 0; im < 8; im++)
#pragma unroll
                for (int in = 0; in < 4; in++)
                    acc[im][in] += ar[im] * br[in];
        }
    }

#pragma unroll
    for (int im = 0; im < 8; im++) {
        int m = m0 + ty * 8 + im;
        float nm = g_n2[b * MM + m];
#pragma unroll
        for (int in = 0; in < 4; in++) {
            int n = n0 + tx * 4 + in;
            float d2 = nm + g_n1[b * NN + n] - 2.0f * acc[im][in];
            g_cost[((size_t)b * MM + m) * NN + n] = sqrtf(fmaxf(d2, 0.0f));
        }
    }
}

// ---------------------------------------------------------------------------
// LAPJV (rectangular-safe): row reduction + greedy tight seeding + iterated
// augmenting row reduction (fp32-filtered auction sweeps, v=0 base) + exact
// Dijkstra augmentation. One warp per batch; lane owns [lane*16, lane*16+16).
// ---------------------------------------------------------------------------
#define MAXU64 0xFFFFFFFFFFFFFFFFULL
#define GUARD   1e-4f
#define GUARDB  1e-3f    // B2 candidate slack (fp32 drift <= ~2e-5)
#define GUARDB_D 1e-3    // B2 u2 lower-bound margin
#define ARR_SWEEPS 96

__device__ __forceinline__ unsigned long long dsort(double d) {
    long long x = __double_as_longlong(d);
    return (unsigned long long)(x ^ ((x >> 63) | 0x8000000000000000LL));
}
__device__ __forceinline__ double dunsort(unsigned long long u) {
    long long x = (long long)u;
    long long b = (x < 0) ? (x ^ 0x8000000000000000LL) : ~x;
    return __longlong_as_double(b);
}
__device__ __forceinline__ unsigned fsort(float x) {
    unsigned bb = __float_as_uint(x);
    return bb ^ (unsigned)(((int)bb >> 31) | 0x80000000);
}

// load this lane's 16 contiguous floats of a cost row (4x LDG.128)
__device__ __forceinline__ void load_row16(const float* crow, int lane, float* f) {
    const float4* r4 = (const float4*)(crow + lane * 16);
    float4 q0 = __ldg(r4 + 0);
    float4 q1 = __ldg(r4 + 1);
    float4 q2 = __ldg(r4 + 2);
    float4 q3 = __ldg(r4 + 3);
    f[0] = q0.x;  f[1] = q0.y;  f[2]  = q0.z;  f[3]  = q0.w;
    f[4] = q1.x;  f[5] = q1.y;  f[6]  = q1.z;  f[7]  = q1.w;
    f[8] = q2.x;  f[9] = q2.y;  f[10] = q2.z;  f[11] = q2.w;
    f[12] = q3.x; f[13] = q3.y; f[14] = q3.z;  f[15] = q3.w;
}

__global__ void __launch_bounds__(32) jv_warp_kernel() {
    __shared__ double u[MM + 1];     // row potentials
    __shared__ double sarr[NN];      // D at marking time, per column
    __shared__ int    p[NN + 1];     // column -> assigned row (1-based), 0=free
    __shared__ int    way[NN + 1];
    __shared__ int    argcol[MM + 1];// row -> argmin column (1-based)
    __shared__ int    freelist[MM];

    int b = blockIdx.x;
    const float* cbase = g_cost + (size_t)b * MM * NN;
    int lane = threadIdx.x;

    for (int t = lane; t < NN + 1; t += 32) { p[t] = 0; way[t] = 0; }
    __syncwarp();

    // per-lane duals for owned columns (v = 0 base everywhere)
    double v[16];
    float  vf[16];
#pragma unroll
    for (int c = 0; c < 16; c++) { v[c] = 0.0; vf[c] = 0.0f; }

    // ---- Phase A: row reduction  u[i] = min_j c[i][j], record argmin -----
    for (int i = 1; i <= MM; i++) {
        const float* crow = cbase + (size_t)(i - 1) * NN;
        float f[16];
        load_row16(crow, lane, f);
        float m = 3.0e38f;
        int bj = 0x7fffffff;
#pragma unroll
        for (int c = 0; c < 16; c++)
            if (f[c] < m) { m = f[c]; bj = lane * 16 + c; }
#pragma unroll
        for (int o = 16; o > 0; o >>= 1) {
            float om = __shfl_xor_sync(FULL, m, o);
            int obj = __shfl_xor_sync(FULL, bj, o);
            if (om < m || (om == m && obj < bj)) { m = om; bj = obj; }
        }
        if (lane == 0) { u[i] = (double)m; argcol[i] = bj + 1; }
    }
    __syncwarp();

    // ---- Phase B: greedy tight seeding (lane 0, serial) ------------------
    int numfree = 0;
    if (lane == 0) {
        for (int i = 1; i <= MM; i++) {
            int j = argcol[i];
            if (p[j] == 0) p[j] = i;       // tight: c - u - 0 == 0
            else           freelist[numfree++] = i;
        }
    }
    numfree = __shfl_sync(FULL, numfree, 0);
    __syncwarp();

    // ---- Phase B2: fp32-filtered auction sweeps (eps=0, v=0 base) --------
    // u1/argmin computed EXACTLY (fp64) over the fp32 candidate set, which
    // provably contains the exact argmin. u2 is replaced by a guaranteed
    // LOWER BOUND (m2f - GUARDB_D): u[fr] <= all reduced costs keeps dual
    // feasibility; tightness of (fr, j1) holds by construction since
    // v[j1] -= max(0, u2_safe - u1). Free columns keep v = 0 forever.
    for (int sweep = 0; sweep < ARR_SWEEPS && numfree > 0; sweep++) {
        int prv = numfree;
        int nf2 = 0;
        for (int k = 0; k < prv; k++) {
            int fr = freelist[k];
            const float* crow = cbase + (size_t)(fr - 1) * NN;
            float f[16];
            load_row16(crow, lane, f);

            // fp32 lane-local min1/min2 of reduced costs
            float curf[16];
            float m1f = 3.0e38f, m2f = 3.0e38f;
#pragma unroll
            for (int c = 0; c < 16; c++) {
                float cf = f[c] - vf[c];
                curf[c] = cf;
                if (cf < m1f) { m2f = m1f; m1f = cf; }
                else if (cf < m2f) m2f = cf;
            }
            // warp merge (values only; 2 x 32-bit shuffles per step)
#pragma unroll
            for (int o = 16; o > 0; o >>= 1) {
                float om1 = __shfl_xor_sync(FULL, m1f, o);
                float om2 = __shfl_xor_sync(FULL, m2f, o);
                if (om1 < m1f) { m2f = fminf(m1f, om2); m1f = om1; }
                else           { m2f = fminf(m2f, om1); }
            }

            // exact fp64 eval restricted to argmin candidates
            float T = m1f + GUARDB;
            unsigned cmask = 0;
#pragma unroll
            for (int c = 0; c < 16; c++)
                if (curf[c] <= T) cmask |= 1u << c;
            unsigned long long em1 = MAXU64;
            int ebj = 0x7fffffff;
            while (cmask) {
                int c = __ffs(cmask) - 1;
                cmask &= cmask - 1;
                unsigned long long cs = dsort((double)f[c] - v[c]);
                if (cs < em1) { em1 = cs; ebj = lane * 16 + c; } // asc c: first wins
            }
            // gather candidate lanes (warp-uniform merge, lowest-j tie-break)
            unsigned lanes = __ballot_sync(FULL, em1 != MAXU64);
            unsigned long long bm1 = MAXU64;
            int bj = 0x7fffffff;
            while (lanes) {
                int l = __ffs(lanes) - 1;
                lanes &= lanes - 1;
                unsigned long long cm = __shfl_sync(FULL, em1, l);
                int cb = __shfl_sync(FULL, ebj, l);
                if (cm < bm1 || (cm == bm1 && cb < bj)) { bm1 = cm; bj = cb; }
            }
            int j1 = bj + 1;                 // warp-uniform
            double u1 = dunsort(bm1);
            double u2s = (double)m2f - GUARDB_D;   // lower bound on true min2
            double adj = u2s - u1;
            if (adj < 0.0) { adj = 0.0; u2s = u1; }

            int i1 = p[j1];                  // ALL lanes read first...
            __syncwarp();                    // ...ordered before writes
            if (lane == 0) {
                u[fr] = u2s;                 // feasible (+tight on j1)
                p[j1] = fr;
            }
            if ((adj > 0.0) && lane == (bj >> 4)) {
                v[bj & 15] -= adj;
                vf[bj & 15] = (float)v[bj & 15];
            }
            __syncwarp();
            if (i1) {                        // uniform across warp
                if (lane == 0) freelist[nf2] = i1;
                nf2++;
                __syncwarp();
            }
        }
        numfree = nf2;
    }
    __syncwarp();

    // ---- Phase C: exact Dijkstra augmentation ----------------------------
    for (int t = 0; t < numfree; t++) {
        int i = freelist[t];

        unsigned long long msort[16];   // exact sorted-bits of minv (shifted)
        float minvf[16];                // fp32 approx of minv
        float thr[16];                  // filter threshold = minvf + vf + GUARD
#pragma unroll
        for (int c = 0; c < 16; c++) {
            msort[c] = MAXU64; minvf[c] = 3.0e38f; thr[c] = 3.0e38f;
        }
        unsigned long long lmin = MAXU64;
        float lminf = 3.0e38f;
        int lidx = 0;
        unsigned umask = 0;
        double D = 0.0;
        int i0 = i;
        int j0 = 0;
        if (lane == 0) p[0] = i;
        __syncwarp();

        int jsel;
        double Df;

        while (true) {
            double h = D - u[i0];
            float hf = (float)h;
            const float* crow = cbase + (size_t)(i0 - 1) * NN;

            float f[16];
            load_row16(crow, lane, f);

            unsigned pmask = 0;
#pragma unroll
            for (int c = 0; c < 16; c++)
                if (f[c] + hf < thr[c]) pmask |= 1u << c;

            while (pmask) {
                int c = __ffs(pmask) - 1;
                pmask &= pmask - 1;
                double cur = ((double)f[c] + h) - v[c];
                unsigned long long cs = dsort(cur);
                if (cs < msort[c]) {
                    msort[c] = cs;
                    minvf[c] = (float)cur;
                    thr[c]   = minvf[c] + vf[c] + GUARD;
                    way[lane * 16 + c + 1] = j0;
                    if (cs < lmin) { lmin = cs; lidx = c; lminf = minvf[c]; }
                }
            }

            // warp argmin: fp32-proxy REDUX + exact resolution among the
            // (usually single) candidate lane(s).
            unsigned pb = fsort(lminf);
            unsigned pm = __reduce_min_sync(FULL, pb);
            unsigned bal = __ballot_sync(FULL, pb == pm);
            int wl = __ffs(bal) - 1;
            unsigned long long wsv = __shfl_sync(FULL, lmin, wl);
            unsigned rest = bal & (bal - 1);
            while (rest) {
                int l2 = __ffs(rest) - 1; rest &= rest - 1;
                unsigned long long cand = __shfl_sync(FULL, lmin, l2);
                if (cand < wsv) { wsv = cand; wl = l2; }
            }
            int widx = __shfl_sync(FULL, lidx, wl);
            int j1 = wl * 16 + widx + 1;

            double Dnew = dunsort(wsv);
            D = Dnew;

            int pj1 = p[j1];           // broadcast LDS, warp-uniform
            if (pj1 == 0) { jsel = j1; Df = Dnew; break; }

            if (lane == wl) {
                umask |= 1u << widx;
                msort[widx] = MAXU64;
                minvf[widx] = -3.0e38f;
                thr[widx]   = -3.0e38f;
                sarr[j1 - 1] = Dnew;
                lmin = MAXU64; lidx = 0; lminf = 3.0e38f;
#pragma unroll
                for (int c2 = 0; c2 < 16; c2++)
                    if (msort[c2] < lmin) {
                        lmin = msort[c2]; lidx = c2; lminf = minvf[c2];
                    }
            }
            i0 = pj1;
            j0 = j1;
        }

        // deferred dual updates (p[] is pre-augmentation; only USED = matched
        // columns get v updates, so free columns keep v = 0 forever)
        unsigned um = umask;
        while (um) {
            int c = __ffs(um) - 1; um &= um - 1;
            int j = lane * 16 + c + 1;
            double adj = Df - sarr[j - 1];
            v[c] -= adj;
            vf[c] = (float)v[c];
            int r = p[j];
            u[r] += adj;
        }
        if (lane == 0) u[i] += Df;
        __syncwarp();

        if (lane == 0) {
            int j0a = jsel;
            while (j0a) { int jp = way[j0a]; p[j0a] = p[jp]; j0a = jp; }
        }
        __syncwarp();
    }

    // perm: matched original rows ascending, then unmatched ascending
    int mbase = b * NN, mo = 0, uo = MM;
#pragma unroll
    for (int g = 0; g < 16; g++) {
        int j = g * 32 + lane + 1;
        bool mt = (p[j] != 0);
        unsigned bal = __ballot_sync(FULL, mt);
        unsigned ltm = (lane == 0) ? 0u : (FULL >> (32 - lane));
        int lt  = __popc(bal & ltm);
        int ltu = __popc((~bal) & ltm);
        if (mt)  g_perm[mbase + mo + lt]  = j - 1;
        if (!mt) g_perm[mbase + uo + ltu] = j - 1;
        mo += __popc(bal);
        uo += 32 - __popc(bal);
    }
}

// ---------------------------------------------------------------------------
// Gather: out[b][k] = seq1[b][perm[b][k]]
// ---------------------------------------------------------------------------
__global__ void gather_kernel(const float* __restrict__ seq1,
                              float* __restrict__ out) {
    int b   = blockIdx.y;
    int row = blockIdx.x;
    int src = g_perm[b * NN + row];
    const float4* s = (const float4*)(seq1 + ((size_t)b * NN + src) * DD);
    float4*       d = (float4*)(out  + ((size_t)b * NN + row) * DD);
    int k = threadIdx.x;
    d[k] = s[k];
}

// ---------------------------------------------------------------------------
extern "C" void kernel_launch(void* const* d_in, const int* in_sizes, int n_in,
                              void* d_out, int out_size) {
    const float* seq1 = (const float*)d_in[0];
    const float* seq2 = (const float*)d_in[1];
    float* out = (float*)d_out;

    int totalRows = BB * (NN + MM);
    norms_kernel<<<totalRows / 8, 256>>>(seq1, seq2);

    dim3 gc(NN / TBN, MM / TBM, BB);                // (4, 7, 16)
    cost_kernel<<<gc, 256>>>(seq1, seq2);

    jv_warp_kernel<<<BB, 32>>>();

    gather_kernel<<<dim3(NN, BB), DD / 4>>>(seq1, out);
}

// round 17
// speedup vs baseline: 1.2306x; 1.2306x over previous
#include <cuda_runtime.h>

#define BB 16
#define NN 512   // seq1 rows (columns of transposed cost)
#define MM 448   // seq2 rows (rows of transposed cost)
#define DD 1536
#define FULL 0xffffffffu

// cost_t[b][m][n] = ||seq1[b][n] - seq2[b][m]||  (transposed layout for JV)
__device__ float g_cost[BB * MM * NN];
__device__ float g_n1[BB * NN];
__device__ float g_n2[BB * MM];
__device__ int   g_perm[BB * NN];
// packed row minima: (fsort(value) << 32) | argmin_col   (atomicMin-reduced)
__device__ unsigned long long g_rowmin[BB * MM];

__device__ __forceinline__ unsigned fsort_h(float x) {
    unsigned bb = __float_as_uint(x);
    return bb ^ (unsigned)(((int)bb >> 31) | 0x80000000);
}

// ---------------------------------------------------------------------------
// Row norms: one warp per row. Also initializes g_rowmin.
// ---------------------------------------------------------------------------
__global__ void norms_kernel(const float* __restrict__ seq1,
                             const float* __restrict__ seq2) {
    int gtid = blockIdx.x * blockDim.x + threadIdx.x;
    if (gtid < BB * MM) g_rowmin[gtid] = 0xFFFFFFFFFFFFFFFFULL;

    int warp = gtid >> 5;
    int lane = threadIdx.x & 31;
    int total = BB * (NN + MM);
    if (warp >= total) return;
    const float* ptr;
    float* out;
    if (warp < BB * NN) {
        ptr = seq1 + (size_t)warp * DD;
        out = g_n1 + warp;
    } else {
        int w = warp - BB * NN;
        ptr = seq2 + (size_t)w * DD;
        out = g_n2 + w;
    }
    float s = 0.f;
    for (int k = lane * 4; k < DD; k += 32 * 4) {
        float4 v = *(const float4*)(ptr + k);
        s += v.x * v.x + v.y * v.y + v.z * v.z + v.w * v.w;
    }
#pragma unroll
    for (int o = 16; o > 0; o >>= 1) s += __shfl_down_sync(FULL, s, o);
    if (lane == 0) *out = s;
}

// ---------------------------------------------------------------------------
// Cost matrix: tiled fp32 GEMM, 64(m) x 128(n) tile, 8x4 per thread.
// Epilogue also reduces per-row (min, argmin) into g_rowmin via atomicMin
// on packed u64 (value-sortable hi, col lo -> lowest-col tie-break).
// ---------------------------------------------------------------------------
#define TBM 64
#define TBN 128
#define TBK 16

__global__ void __launch_bounds__(256) cost_kernel(const float* __restrict__ seq1,
                                                   const float* __restrict__ seq2) {
    __shared__ float As[TBK][TBM + 4];
    __shared__ float Bs[TBK][TBN + 4];

    int b  = blockIdx.z;
    int m0 = blockIdx.y * TBM;
    int n0 = blockIdx.x * TBN;
    const float* A  = seq2 + ((size_t)b * MM + m0) * DD;
    const float* Bp = seq1 + ((size_t)b * NN + n0) * DD;

    int tid = threadIdx.x;
    int lr  = tid >> 2;          // 0..63
    int lc  = (tid & 3) * 4;     // 0,4,8,12
    int ty  = tid >> 5;          // 0..7  (== warp id)
    int tx  = tid & 31;          // 0..31

    float acc[8][4] = {};

    for (int k0 = 0; k0 < DD; k0 += TBK) {
        float4 av  = *(const float4*)(A  + (size_t)lr * DD + k0 + lc);
        float4 bv0 = *(const float4*)(Bp + (size_t)lr * DD + k0 + lc);
        float4 bv1 = *(const float4*)(Bp + (size_t)(lr + 64) * DD + k0 + lc);
        __syncthreads();
        As[lc + 0][lr] = av.x;  As[lc + 1][lr] = av.y;
        As[lc + 2][lr] = av.z;  As[lc + 3][lr] = av.w;
        Bs[lc + 0][lr] = bv0.x; Bs[lc + 1][lr] = bv0.y;
        Bs[lc + 2][lr] = bv0.z; Bs[lc + 3][lr] = bv0.w;
        Bs[lc + 0][lr + 64] = bv1.x; Bs[lc + 1][lr + 64] = bv1.y;
        Bs[lc + 2][lr + 64] = bv1.z; Bs[lc + 3][lr + 64] = bv1.w;
        __syncthreads();
#pragma unroll
        for (int k = 0; k < TBK; k++) {
            float4 a0 = *(const float4*)&As[k][ty * 8];
            float4 a1 = *(const float4*)&As[k][ty * 8 + 4];
            float4 bb = *(const float4*)&Bs[k][tx * 4];
            float ar[8] = {a0.x, a0.y, a0.z, a0.w, a1.x, a1.y, a1.z, a1.w};
            float br[4] = {bb.x, bb.y, bb.z, bb.w};
#pragma unroll
            for (int im = 0; im < 8; im++)
#pragma unroll
                for (int in = 0; in < 4; in++)
                    acc[im][in] += ar[im] * br[in];
        }
    }

#pragma unroll
    for (int im = 0; im < 8; im++) {
        int m = m0 + ty * 8 + im;
        float nm = g_n2[b * MM + m];
        unsigned long long pk = 0xFFFFFFFFFFFFFFFFULL;
#pragma unroll
        for (int in = 0; in < 4; in++) {
            int n = n0 + tx * 4 + in;
            float d2 = nm + g_n1[b * NN + n] - 2.0f * acc[im][in];
            float c = sqrtf(fmaxf(d2, 0.0f));
            g_cost[((size_t)b * MM + m) * NN + n] = c;
            unsigned long long cand =
                ((unsigned long long)fsort_h(c) << 32) | (unsigned)n;
            if (cand < pk) pk = cand;
        }
        // warp reduce (all 32 lanes of warp ty hold the same row m)
#pragma unroll
        for (int o = 16; o > 0; o >>= 1) {
            unsigned long long op = __shfl_xor_sync(FULL, pk, o);
            if (op < pk) pk = op;
        }
        if (tx == 0) atomicMin(&g_rowmin[b * MM + m], pk);
    }
}

// ---------------------------------------------------------------------------
// LAPJV (rectangular-safe): fused row reduction + greedy tight seeding +
// iterated augmenting row reduction (exact auction sweeps, v=0 base) +
// exact Dijkstra augmentation. One warp per batch; lane owns
// contiguous columns [lane*16, lane*16+16).
// ---------------------------------------------------------------------------
#define MAXU64 0xFFFFFFFFFFFFFFFFULL
#define GUARD  1e-4f
#define ARR_SWEEPS 64

__device__ __forceinline__ unsigned long long dsort(double d) {
    long long x = __double_as_longlong(d);
    return (unsigned long long)(x ^ ((x >> 63) | 0x8000000000000000LL));
}
__device__ __forceinline__ double dunsort(unsigned long long u) {
    long long x = (long long)u;
    long long b = (x < 0) ? (x ^ 0x8000000000000000LL) : ~x;
    return __longlong_as_double(b);
}
__device__ __forceinline__ unsigned fsort(float x) {
    unsigned bb = __float_as_uint(x);
    return bb ^ (unsigned)(((int)bb >> 31) | 0x80000000);
}
__device__ __forceinline__ float funsort(unsigned x) {
    unsigned bb = (x & 0x80000000u) ? (x ^ 0x80000000u) : ~x;
    return __uint_as_float(bb);
}

// load this lane's 16 contiguous floats of a cost row (4x LDG.128)
__device__ __forceinline__ void load_row16(const float* crow, int lane, float* f) {
    const float4* r4 = (const float4*)(crow + lane * 16);
    float4 q0 = __ldg(r4 + 0);
    float4 q1 = __ldg(r4 + 1);
    float4 q2 = __ldg(r4 + 2);
    float4 q3 = __ldg(r4 + 3);
    f[0] = q0.x;  f[1] = q0.y;  f[2]  = q0.z;  f[3]  = q0.w;
    f[4] = q1.x;  f[5] = q1.y;  f[6]  = q1.z;  f[7]  = q1.w;
    f[8] = q2.x;  f[9] = q2.y;  f[10] = q2.z;  f[11] = q2.w;
    f[12] = q3.x; f[13] = q3.y; f[14] = q3.z;  f[15] = q3.w;
}

__global__ void __launch_bounds__(32) jv_warp_kernel() {
    __shared__ double u[MM + 1];     // row potentials
    __shared__ double sarr[NN];      // D at marking time, per column
    __shared__ int    p[NN + 1];     // column -> assigned row (1-based), 0=free
    __shared__ int    way[NN + 1];
    __shared__ int    argcol[MM + 1];// row -> argmin column (1-based)
    __shared__ int    freelist[MM];

    int b = blockIdx.x;
    const float* cbase = g_cost + (size_t)b * MM * NN;
    int lane = threadIdx.x;

    for (int t = lane; t < NN + 1; t += 32) { p[t] = 0; way[t] = 0; }
    __syncwarp();

    // per-lane duals for owned columns (v = 0 base everywhere)
    double v[16];
#pragma unroll
    for (int c = 0; c < 16; c++) v[c] = 0.0;

    // ---- Phase A (fused): read row minima computed by cost_kernel --------
    for (int t = lane; t < MM; t += 32) {
        unsigned long long rm = g_rowmin[b * MM + t];
        u[t + 1] = (double)funsort((unsigned)(rm >> 32));
        argcol[t + 1] = (int)(rm & 0xFFFFFFFFu) + 1;
    }
    __syncwarp();

    // ---- Phase B: greedy tight seeding (lane 0, serial) ------------------
    int numfree = 0;
    if (lane == 0) {
        for (int i = 1; i <= MM; i++) {
            int j = argcol[i];
            if (p[j] == 0) p[j] = i;       // tight: c - u - 0 == 0
            else           freelist[numfree++] = i;
        }
    }
    numfree = __shfl_sync(FULL, numfree, 0);
    __syncwarp();

    // ---- Phase B2: iterated augmenting row reduction (auction sweeps) ----
    // Gauss-Seidel auction, eps=0, v=0 base: v changes only on a column at
    // the moment it gets (re)matched; matched columns never unmatch -> free
    // columns keep v = 0 (the rectangular-duality invariant).
    // Software-pipelined: row k+1 is prefetched while processing row k
    // (freelist[k+1] is stable during iteration k: in-place writes land at
    // nf2 <= k).
    for (int sweep = 0; sweep < ARR_SWEEPS && numfree > 0; sweep++) {
        int prv = numfree;
        int nf2 = 0;
        float fcur[16], fnext[16];
        if (prv > 0)
            load_row16(cbase + (size_t)(freelist[0] - 1) * NN, lane, fcur);
        for (int k = 0; k < prv; k++) {
            int fr = freelist[k];
            if (k + 1 < prv)
                load_row16(cbase + (size_t)(freelist[k + 1] - 1) * NN, lane, fnext);

            unsigned long long m1 = MAXU64, m2 = MAXU64;
            int bj = 0x7fffffff;
#pragma unroll
            for (int c = 0; c < 16; c++) {
                double cur = (double)fcur[c] - v[c];
                unsigned long long cs = dsort(cur);
                if (cs < m1) { m2 = m1; m1 = cs; bj = lane * 16 + c; }
                else if (cs < m2) m2 = cs;
            }
            // warp merge of (min1, argmin1, min2); index tie-break keeps
            // ALL lanes converged on the same bj even on exact ties.
#pragma unroll
            for (int o = 16; o > 0; o >>= 1) {
                unsigned long long om1 = __shfl_xor_sync(FULL, m1, o);
                unsigned long long om2 = __shfl_xor_sync(FULL, m2, o);
                int obj = __shfl_xor_sync(FULL, bj, o);
                bool take = (om1 < m1) || (om1 == m1 && obj < bj);
                unsigned long long ca = take ? om2 : m2;
                unsigned long long cb = take ? m1  : om1;
                if (take) { m1 = om1; bj = obj; }
                m2 = (cb < ca) ? cb : ca;
            }
            int j1 = bj + 1;                 // warp-uniform
            double u1 = dunsort(m1);
            double u2 = dunsort(m2);

            int i1 = p[j1];                  // ALL lanes read first...
            __syncwarp();                    // ...ordered before writes
            if (lane == 0) {
                u[fr] = u2;                  // tight (+feasible)
                p[j1] = fr;
            }
            // v[j1] -= (u2 - u1) on the owning lane's register copy
            if ((m1 < m2) && lane == (bj >> 4)) v[bj & 15] -= (u2 - u1);
            __syncwarp();
            if (i1) {                        // uniform across warp
                if (lane == 0) freelist[nf2] = i1;
                nf2++;
                __syncwarp();
            }
#pragma unroll
            for (int c = 0; c < 16; c++) fcur[c] = fnext[c];
        }
        numfree = nf2;
    }
    __syncwarp();

    float vf[16];
#pragma unroll
    for (int c = 0; c < 16; c++) vf[c] = (float)v[c];

    // ---- Phase C: exact Dijkstra augmentation ----------------------------
    for (int t = 0; t < numfree; t++) {
        int i = freelist[t];

        unsigned long long msort[16];   // exact sorted-bits of minv (shifted)
        float minvf[16];                // fp32 approx of minv
        float thr[16];                  // filter threshold = minvf + vf + GUARD
#pragma unroll
        for (int c = 0; c < 16; c++) {
            msort[c] = MAXU64; minvf[c] = 3.0e38f; thr[c] = 3.0e38f;
        }
        unsigned long long lmin = MAXU64;
        float lminf = 3.0e38f;          // fp32 proxy of the lane's exact min
        int lidx = 0;
        unsigned umask = 0;
        double D = 0.0;
        int i0 = i;
        int j0 = 0;
        if (lane == 0) p[0] = i;
        __syncwarp();

        int jsel;
        double Df;

        while (true) {
            double h = D - u[i0];
            float hf = (float)h;
            const float* crow = cbase + (size_t)(i0 - 1) * NN;

            float f[16];
            load_row16(crow, lane, f);

            // fp32 filter: 1 FADD + 1 FSETP per column
            unsigned pmask = 0;
#pragma unroll
            for (int c = 0; c < 16; c++)
                if (f[c] + hf < thr[c]) pmask |= 1u << c;

            // exact fp64 updates only for filtered columns
            while (pmask) {
                int c = __ffs(pmask) - 1;
                pmask &= pmask - 1;
                double cur = ((double)f[c] + h) - v[c];
                unsigned long long cs = dsort(cur);
                if (cs < msort[c]) {
                    msort[c] = cs;
                    minvf[c] = (float)cur;
                    thr[c]   = minvf[c] + vf[c] + GUARD;
                    way[lane * 16 + c + 1] = j0;
                    if (cs < lmin) { lmin = cs; lidx = c; lminf = minvf[c]; }
                }
            }

            // warp argmin: fp32-proxy REDUX (monotone rounding -> proxy-min
            // set contains the exact argmin) + exact fp64 resolution among
            // the (usually single) candidate lane(s).
            unsigned pb = fsort(lminf);
            unsigned pm = __reduce_min_sync(FULL, pb);
            unsigned bal = __ballot_sync(FULL, pb == pm);
            int wl = __ffs(bal) - 1;
            unsigned long long wsv = __shfl_sync(FULL, lmin, wl);
            unsigned rest = bal & (bal - 1);
            while (rest) {                       // rare: proxy tie
                int l2 = __ffs(rest) - 1; rest &= rest - 1;
                unsigned long long cand = __shfl_sync(FULL, lmin, l2);
                if (cand < wsv) { wsv = cand; wl = l2; }
            }
            int widx = __shfl_sync(FULL, lidx, wl);
            int j1 = wl * 16 + widx + 1;

            double Dnew = dunsort(wsv);
            D = Dnew;

            int pj1 = p[j1];           // broadcast LDS, warp-uniform
            if (pj1 == 0) { jsel = j1; Df = Dnew; break; }

            // mark j1 used (winner lane only) + rebuild its local min
            if (lane == wl) {
                umask |= 1u << widx;
                msort[widx] = MAXU64;
                minvf[widx] = -3.0e38f;
                thr[widx]   = -3.0e38f;    // filter can never pass again
                sarr[j1 - 1] = Dnew;
                lmin = MAXU64; lidx = 0; lminf = 3.0e38f;
#pragma unroll
                for (int c2 = 0; c2 < 16; c2++)
                    if (msort[c2] < lmin) {
                        lmin = msort[c2]; lidx = c2; lminf = minvf[c2];
                    }
            }
            i0 = pj1;
            j0 = j1;
        }

        // deferred dual updates (p[] is pre-augmentation; only USED = matched
        // columns get v updates, so free columns keep v = 0 forever)
        unsigned um = umask;
        while (um) {
            int c = __ffs(um) - 1; um &= um - 1;
            int j = lane * 16 + c + 1;
            double adj = Df - sarr[j - 1];
            v[c] -= adj;
            vf[c] = (float)v[c];
            int r = p[j];              // distinct rows across used columns
            u[r] += adj;
        }
        if (lane == 0) u[i] += Df;
        __syncwarp();

        if (lane == 0) {
            int j0a = jsel;
            while (j0a) { int jp = way[j0a]; p[j0a] = p[jp]; j0a = jp; }
        }
        __syncwarp();
    }

    // perm: matched original rows ascending, then unmatched ascending
    int mbase = b * NN, mo = 0, uo = MM;
#pragma unroll
    for (int g = 0; g < 16; g++) {
        int j = g * 32 + lane + 1;
        bool mt = (p[j] != 0);
        unsigned bal = __ballot_sync(FULL, mt);
        unsigned ltm = (lane == 0) ? 0u : (FULL >> (32 - lane));
        int lt  = __popc(bal & ltm);
        int ltu = __popc((~bal) & ltm);
        if (mt)  g_perm[mbase + mo + lt]  = j - 1;
        if (!mt) g_perm[mbase + uo + ltu] = j - 1;
        mo += __popc(bal);
        uo += 32 - __popc(bal);
    }
}

// ---------------------------------------------------------------------------
// Gather: out[b][k] = seq1[b][perm[b][k]]
// ---------------------------------------------------------------------------
__global__ void gather_kernel(const float* __restrict__ seq1,
                              float* __restrict__ out) {
    int b   = blockIdx.y;
    int row = blockIdx.x;
    int src = g_perm[b * NN + row];
    const float4* s = (const float4*)(seq1 + ((size_t)b * NN + src) * DD);
    float4*       d = (float4*)(out  + ((size_t)b * NN + row) * DD);
    int k = threadIdx.x;
    d[k] = s[k];
}

// ---------------------------------------------------------------------------
extern "C" void kernel_launch(void* const* d_in, const int* in_sizes, int n_in,
                              void* d_out, int out_size) {
    const float* seq1 = (const float*)d_in[0];
    const float* seq2 = (const float*)d_in[1];
    float* out = (float*)d_out;

    int totalRows = BB * (NN + MM);
    norms_kernel<<<totalRows / 8, 256>>>(seq1, seq2);

    dim3 gc(NN / TBN, MM / TBM, BB);                // (4, 7, 16)
    cost_kernel<<<gc, 256>>>(seq1, seq2);

    jv_warp_kernel<<<BB, 32>>>();

    gather_kernel<<<dim3(NN, BB), DD / 4>>>(seq1, out);
}